// round 9
// baseline (speedup 1.0000x reference)
#include <cuda_runtime.h>

#define N_AG 64
#define HW 8
#define BLK 128
#define SEG_AG 16          // agents per thread (quarter-ring segment)

__device__ __forceinline__ float htanh(float v) {
    float y;
    asm("tanh.approx.f32 %0, %1;" : "=f"(y) : "f"(v));
    return y;
}

// Coupling for one edge, all fp32 (bc2 cancels in the ring difference).
__device__ __forceinline__ float coup(float xs, float xn,
                                      const float* A0, const float* A1,
                                      const float* CB, const float* CW)
{
    float cc = 0.f;
    #pragma unroll
    for (int h = 0; h < HW; h++)
        cc = fmaf(htanh(fmaf(xs, A0[h], fmaf(xn, A1[h], CB[h]))), CW[h], cc);
    return cc;
}

__global__ void __launch_bounds__(BLK)
ode_kernel(const float* __restrict__ x,
           const float* __restrict__ W1, const float* __restrict__ B1,
           const float* __restrict__ W2, const float* __restrict__ B2,
           const float* __restrict__ Wc1, const float* __restrict__ Bc1,
           const float* __restrict__ Wc2,
           float* __restrict__ out, int nrows, int rstride)
{
    // Per-agent weights in shared: uniform-broadcast LDS.128, each read
    // amortized over TWO rows per thread.
    __shared__ float4 sW1[N_AG * 2], sB1[N_AG * 2], sW2[N_AG * 2];
    __shared__ float  sB2[N_AG];

    int tid = threadIdx.x;
    sW1[tid] = ((const float4*)W1)[tid];
    sB1[tid] = ((const float4*)B1)[tid];
    sW2[tid] = ((const float4*)W2)[tid];
    if (tid < N_AG) sB2[tid] = B2[tid];

    // Coupling constants hoisted to registers (uniform loads, L1-cached)
    float A0[HW], A1[HW], CB[HW], CW[HW];
    #pragma unroll
    for (int h = 0; h < HW; h++) {
        A0[h] = Wc1[h];        // weight on x_send
        A1[h] = Wc1[HW + h];   // weight on x_recv
        CB[h] = Bc1[h];
        CW[h] = Wc2[h];
    }
    __syncthreads();

    int rowA = (blockIdx.x >> 2) * BLK + tid;  // block-uniform segment keeps
    int seg  = blockIdx.x & 3;                 // weight indices warp-uniform
    if (rowA >= rstride) return;
    int rowB = rowA + rstride;
    if (rowB >= nrows) rowB = rowA;            // odd-tail: duplicate (deterministic)

    const float* xrowA = x + (size_t)rowA * N_AG;
    const float* xrowB = x + (size_t)rowB * N_AG;
    int n0 = seg * SEG_AG;

    const float4* xrA = (const float4*)xrowA + (n0 >> 2);
    const float4* xrB = (const float4*)xrowB + (n0 >> 2);
    float4* outA = (float4*)(out + (size_t)rowA * N_AG) + (n0 >> 2);
    float4* outB = (float4*)(out + (size_t)rowB * N_AG) + (n0 >> 2);

    float xPrevA = xrowA[(n0 + 63) & 63],  xNextA = xrowA[(n0 + SEG_AG) & 63];
    float xPrevB = xrowB[(n0 + 63) & 63],  xNextB = xrowB[(n0 + SEG_AG) & 63];

    float4 curA = xrA[0], curB = xrB[0];

    // interactions[n] = contrib[n-1] - contrib[n]; seed carries with contrib[n0-1]
    float cprevA = coup(xPrevA, curA.x, A0, A1, CB, CW);
    float cprevB = coup(xPrevB, curB.x, A0, A1, CB, CW);

    #pragma unroll
    for (int c = 0; c < 4; c++) {
        float4 nxtA, nxtB;
        float nA0, nB0;
        if (c < 3) { nxtA = xrA[c+1]; nxtB = xrB[c+1]; nA0 = nxtA.x; nB0 = nxtB.x; }
        else       { nA0 = xNextA; nB0 = xNextB; }

        float xvA[5] = {curA.x, curA.y, curA.z, curA.w, nA0};
        float xvB[5] = {curB.x, curB.y, curB.z, curB.w, nB0};

        float resA[4], resB[4];
        #pragma unroll
        for (int j = 0; j < 4; j++) {
            int n = n0 + c * 4 + j;

            // one set of weight LDS serves BOTH rows
            float4 w1a = sW1[n*2], w1b = sW1[n*2+1];
            float4 b1a = sB1[n*2], b1b = sB1[n*2+1];
            float4 w2a = sW2[n*2], w2b = sW2[n*2+1];
            float  bb2 = sB2[n];

            // ---- row A ----
            {
                float xs = xvA[j];
                float cc = coup(xs, xvA[j + 1], A0, A1, CB, CW);
                float acc = bb2;
                acc = fmaf(htanh(fmaf(xs, w1a.x, b1a.x)), w2a.x, acc);
                acc = fmaf(htanh(fmaf(xs, w1a.y, b1a.y)), w2a.y, acc);
                acc = fmaf(htanh(fmaf(xs, w1a.z, b1a.z)), w2a.z, acc);
                acc = fmaf(htanh(fmaf(xs, w1a.w, b1a.w)), w2a.w, acc);
                acc = fmaf(htanh(fmaf(xs, w1b.x, b1b.x)), w2b.x, acc);
                acc = fmaf(htanh(fmaf(xs, w1b.y, b1b.y)), w2b.y, acc);
                acc = fmaf(htanh(fmaf(xs, w1b.z, b1b.z)), w2b.z, acc);
                acc = fmaf(htanh(fmaf(xs, w1b.w, b1b.w)), w2b.w, acc);
                resA[j] = acc + cprevA - cc;
                cprevA = cc;
            }
            // ---- row B ----
            {
                float xs = xvB[j];
                float cc = coup(xs, xvB[j + 1], A0, A1, CB, CW);
                float acc = bb2;
                acc = fmaf(htanh(fmaf(xs, w1a.x, b1a.x)), w2a.x, acc);
                acc = fmaf(htanh(fmaf(xs, w1a.y, b1a.y)), w2a.y, acc);
                acc = fmaf(htanh(fmaf(xs, w1a.z, b1a.z)), w2a.z, acc);
                acc = fmaf(htanh(fmaf(xs, w1a.w, b1a.w)), w2a.w, acc);
                acc = fmaf(htanh(fmaf(xs, w1b.x, b1b.x)), w2b.x, acc);
                acc = fmaf(htanh(fmaf(xs, w1b.y, b1b.y)), w2b.y, acc);
                acc = fmaf(htanh(fmaf(xs, w1b.z, b1b.z)), w2b.z, acc);
                acc = fmaf(htanh(fmaf(xs, w1b.w, b1b.w)), w2b.w, acc);
                resB[j] = acc + cprevB - cc;
                cprevB = cc;
            }
        }

        float4 oA, oB;
        oA.x = resA[0]; oA.y = resA[1]; oA.z = resA[2]; oA.w = resA[3];
        oB.x = resB[0]; oB.y = resB[1]; oB.z = resB[2]; oB.w = resB[3];
        outA[c] = oA;
        outB[c] = oB;
        if (c < 3) { curA = nxtA; curB = nxtB; }
    }
}

extern "C" void kernel_launch(void* const* d_in, const int* in_sizes, int n_in,
                              void* d_out, int out_size)
{
    // metadata order: x, W1, b1, W2, b2, Wc1, bc1, Wc2, bc2, send_idx, recv_idx
    const float* x = (const float*)d_in[0];
    float* out = (float*)d_out;

    int nrows = in_sizes[0] / N_AG;
    int rstride = (nrows + 1) / 2;                 // rows per half-split
    int rowBlocks = (rstride + BLK - 1) / BLK;
    int grid = rowBlocks * 4;                      // 4 ring segments
    ode_kernel<<<grid, BLK>>>(x,
                              (const float*)d_in[1], (const float*)d_in[2],
                              (const float*)d_in[3], (const float*)d_in[4],
                              (const float*)d_in[5], (const float*)d_in[6],
                              (const float*)d_in[7],
                              out, nrows, rstride);
}